// round 1
// baseline (speedup 1.0000x reference)
#include <cuda_runtime.h>
#include <cuda_bf16.h>
#include <mma.h>

using namespace nvcuda;

#define BATCH   4
#define T_SEQ   64
#define NSPAT   196
#define CDIM    768
#define HEADS   12
#define HD      64
#define M_TOT   (BATCH * T_SEQ * NSPAT)   // 50176
#define QKV_N   (3 * CDIM)                // 2304

// Scratch (device globals: allocation-free per harness rules)
__device__ float g_qkv[(size_t)M_TOT * QKV_N];   // 462 MB
__device__ float g_att[(size_t)M_TOT * CDIM];    // 154 MB

// ---------------------------------------------------------------------------
// TF32 WMMA GEMM: C[m][n] = sum_k A[m*K+k] * B[n*K+k]   (both K-major)
// Block tile 128x64, BK=32, 256 threads, 8 warps in 4(m) x 2(n), 32x32 per warp
// ---------------------------------------------------------------------------
#define BM 128
#define BN 64
#define BK 32
#define LDA_S 36
#define LDB_S 36

__global__ void __launch_bounds__(256) gemm_tf32_kernel(
    const float* __restrict__ A, const float* __restrict__ B,
    float* __restrict__ C, int M, int N, int K)
{
    __shared__ float As[BM * LDA_S];
    __shared__ float Bs[BN * LDB_S];

    const int n0 = blockIdx.x * BN;   // N fastest -> A tile reused in L2
    const int m0 = blockIdx.y * BM;

    const int tid  = threadIdx.x;
    const int warp = tid >> 5;
    const int wm   = warp >> 1;  // 0..3
    const int wn   = warp & 1;   // 0..1

    wmma::fragment<wmma::accumulator, 16, 16, 8, float> acc[2][2];
    #pragma unroll
    for (int i = 0; i < 2; i++)
        #pragma unroll
        for (int j = 0; j < 2; j++)
            wmma::fill_fragment(acc[i][j], 0.0f);

    for (int k0 = 0; k0 < K; k0 += BK) {
        // A tile: 128 x 32 = 1024 float4
        #pragma unroll
        for (int i = 0; i < 4; i++) {
            int id = tid + i * 256;
            int m  = id >> 3;
            int k4 = id & 7;
            float4 v = *(const float4*)&A[(size_t)(m0 + m) * K + k0 + k4 * 4];
            *(float4*)&As[m * LDA_S + k4 * 4] = v;
        }
        // B tile: 64 x 32 = 512 float4  (Bs[n][k], col-major fragment view)
        #pragma unroll
        for (int i = 0; i < 2; i++) {
            int id = tid + i * 256;
            int n  = id >> 3;
            int k4 = id & 7;
            float4 v = *(const float4*)&B[(size_t)(n0 + n) * K + k0 + k4 * 4];
            *(float4*)&Bs[n * LDB_S + k4 * 4] = v;
        }
        __syncthreads();

        #pragma unroll
        for (int kk = 0; kk < BK; kk += 8) {
            wmma::fragment<wmma::matrix_a, 16, 16, 8, wmma::precision::tf32, wmma::row_major> af[2];
            wmma::fragment<wmma::matrix_b, 16, 16, 8, wmma::precision::tf32, wmma::col_major> bf[2];
            #pragma unroll
            for (int i = 0; i < 2; i++) {
                wmma::load_matrix_sync(af[i], &As[(wm * 32 + i * 16) * LDA_S + kk], LDA_S);
                #pragma unroll
                for (int t = 0; t < af[i].num_elements; t++)
                    af[i].x[t] = wmma::__float_to_tf32(af[i].x[t]);
            }
            #pragma unroll
            for (int j = 0; j < 2; j++) {
                wmma::load_matrix_sync(bf[j], &Bs[(wn * 32 + j * 16) * LDB_S + kk], LDB_S);
                #pragma unroll
                for (int t = 0; t < bf[j].num_elements; t++)
                    bf[j].x[t] = wmma::__float_to_tf32(bf[j].x[t]);
            }
            #pragma unroll
            for (int i = 0; i < 2; i++)
                #pragma unroll
                for (int j = 0; j < 2; j++)
                    wmma::mma_sync(acc[i][j], af[i], bf[j], acc[i][j]);
        }
        __syncthreads();
    }

    #pragma unroll
    for (int i = 0; i < 2; i++)
        #pragma unroll
        for (int j = 0; j < 2; j++) {
            int mrow = m0 + wm * 32 + i * 16;
            int ncol = n0 + wn * 32 + j * 16;
            wmma::store_matrix_sync(&C[(size_t)mrow * N + ncol], acc[i][j], N,
                                    wmma::mem_row_major);
        }
}

// ---------------------------------------------------------------------------
// Causal attention per (b,h,n): T=64, hd=64. 256 threads, 4x4 per-thread tiles.
// ---------------------------------------------------------------------------
#define LDT 68   // transposed-tile row stride (floats); 68*4B = 272B, 16B aligned

__global__ void __launch_bounds__(256) attn_kernel(
    const float* __restrict__ qkv, float* __restrict__ att)
{
    extern __shared__ float smem[];
    float* sQ = smem;                 // [d][t] stride LDT
    float* sK = smem + 64 * LDT;      // [d][t] stride LDT
    float* sV = smem + 2 * 64 * LDT;  // [t][d] stride 64
    float* sP = sQ;                   // reused: [j][i] stride LDT

    const int blk = blockIdx.x;       // n + NSPAT*(h + HEADS*b)
    const int n = blk % NSPAT;
    const int h = (blk / NSPAT) % HEADS;
    const int b = blk / (NSPAT * HEADS);

    const int tid = threadIdx.x;
    const size_t rowstride = (size_t)NSPAT * QKV_N;
    const size_t base = ((size_t)b * T_SEQ * NSPAT + n) * QKV_N + (size_t)h * HD;

    for (int idx = tid; idx < 64 * 64; idx += 256) {
        int t = idx >> 6;
        int d = idx & 63;
        size_t g = base + (size_t)t * rowstride;
        sQ[d * LDT + t] = qkv[g + d];
        sK[d * LDT + t] = qkv[g + CDIM + d];
        sV[t * 64 + d]  = qkv[g + 2 * CDIM + d];
    }
    __syncthreads();

    const int ti = tid >> 4;  // row group 0..15 -> rows 4*ti..4*ti+3
    const int tj = tid & 15;  // col group 0..15 -> cols 4*tj..4*tj+3

    float accS[16];
    #pragma unroll
    for (int i = 0; i < 16; i++) accS[i] = 0.0f;

    #pragma unroll 4
    for (int d = 0; d < 64; d++) {
        float4 a4 = *(const float4*)&sQ[d * LDT + 4 * ti];
        float4 b4 = *(const float4*)&sK[d * LDT + 4 * tj];
        float av[4] = {a4.x, a4.y, a4.z, a4.w};
        float bv[4] = {b4.x, b4.y, b4.z, b4.w};
        #pragma unroll
        for (int ii = 0; ii < 4; ii++)
            #pragma unroll
            for (int jj = 0; jj < 4; jj++)
                accS[ii * 4 + jj] += av[ii] * bv[jj];
    }

    // scale + causal mask + softmax (rows split across 16 lanes sharing ti)
    const float scale = 0.125f;   // hd^-0.5
    #pragma unroll
    for (int ii = 0; ii < 4; ii++) {
        int i = 4 * ti + ii;
        float mx = -3.402823466e38f;
        #pragma unroll
        for (int jj = 0; jj < 4; jj++) {
            int j = 4 * tj + jj;
            float s = (j <= i) ? accS[ii * 4 + jj] * scale : -3.402823466e38f;
            accS[ii * 4 + jj] = s;
            mx = fmaxf(mx, s);
        }
        #pragma unroll
        for (int m = 8; m >= 1; m >>= 1)
            mx = fmaxf(mx, __shfl_xor_sync(0xffffffffu, mx, m));
        float sum = 0.0f;
        #pragma unroll
        for (int jj = 0; jj < 4; jj++) {
            float e = __expf(accS[ii * 4 + jj] - mx);
            accS[ii * 4 + jj] = e;
            sum += e;
        }
        #pragma unroll
        for (int m = 8; m >= 1; m >>= 1)
            sum += __shfl_xor_sync(0xffffffffu, sum, m);
        float inv = 1.0f / sum;
        #pragma unroll
        for (int jj = 0; jj < 4; jj++) accS[ii * 4 + jj] *= inv;
    }

    __syncthreads();  // all phase-1 reads of sQ done before overwrite
    #pragma unroll
    for (int ii = 0; ii < 4; ii++)
        #pragma unroll
        for (int jj = 0; jj < 4; jj++)
            sP[(4 * tj + jj) * LDT + 4 * ti + ii] = accS[ii * 4 + jj];
    __syncthreads();

    float o[16];
    #pragma unroll
    for (int i = 0; i < 16; i++) o[i] = 0.0f;

    #pragma unroll 4
    for (int j = 0; j < 64; j++) {
        float4 p4 = *(const float4*)&sP[j * LDT + 4 * ti];
        float4 v4 = *(const float4*)&sV[j * 64 + 4 * tj];
        float pv[4] = {p4.x, p4.y, p4.z, p4.w};
        float vv[4] = {v4.x, v4.y, v4.z, v4.w};
        #pragma unroll
        for (int ii = 0; ii < 4; ii++)
            #pragma unroll
            for (int jj = 0; jj < 4; jj++)
                o[ii * 4 + jj] += pv[ii] * vv[jj];
    }

    #pragma unroll
    for (int ii = 0; ii < 4; ii++) {
        int i = 4 * ti + ii;
        size_t addr = (((size_t)b * T_SEQ + i) * NSPAT + n) * CDIM + (size_t)h * HD + 4 * tj;
        float4 o4 = make_float4(o[ii * 4 + 0], o[ii * 4 + 1], o[ii * 4 + 2], o[ii * 4 + 3]);
        *(float4*)&att[addr] = o4;
    }
}

// ---------------------------------------------------------------------------
// Bias add (in place on d_out): out[i] += bias[i % 768], float4 vectorized
// ---------------------------------------------------------------------------
__global__ void __launch_bounds__(256) bias_add_kernel(
    float* __restrict__ out, const float* __restrict__ bias, size_t n4)
{
    size_t i = (size_t)blockIdx.x * 256 + threadIdx.x;
    if (i < n4) {
        float4 v = ((float4*)out)[i];
        int col = (int)((i * 4) % CDIM);
        float4 bv = *(const float4*)&bias[col];
        v.x += bv.x; v.y += bv.y; v.z += bv.z; v.w += bv.w;
        ((float4*)out)[i] = v;
    }
}

// ---------------------------------------------------------------------------
extern "C" void kernel_launch(void* const* d_in, const int* in_sizes, int n_in,
                              void* d_out, int out_size)
{
    const float* x      = (const float*)d_in[0];
    const float* w_qkv  = (const float*)d_in[1];
    const float* w_proj = (const float*)d_in[2];
    const float* b_proj = (const float*)d_in[3];
    float* out = (float*)d_out;

    float* qkv_buf = nullptr;
    float* att_buf = nullptr;
    cudaGetSymbolAddress((void**)&qkv_buf, g_qkv);
    cudaGetSymbolAddress((void**)&att_buf, g_att);

    const int attn_smem = 2 * 64 * LDT * 4 + 64 * 64 * 4;  // 51200 B
    cudaFuncSetAttribute(attn_kernel, cudaFuncAttributeMaxDynamicSharedMemorySize, attn_smem);

    // 1) QKV GEMM: (50176 x 768) @ (2304 x 768)^T
    {
        dim3 grid(QKV_N / BN, M_TOT / BM);   // (36, 392)
        gemm_tf32_kernel<<<grid, 256>>>(x, w_qkv, qkv_buf, M_TOT, QKV_N, CDIM);
    }
    // 2) Attention: one block per (b,h,n)
    {
        dim3 grid(BATCH * HEADS * NSPAT);    // 9408
        attn_kernel<<<grid, 256, attn_smem>>>(qkv_buf, att_buf);
    }
    // 3) Projection GEMM: (50176 x 768) @ (768 x 768)^T -> d_out
    {
        dim3 grid(CDIM / BN, M_TOT / BM);    // (12, 392)
        gemm_tf32_kernel<<<grid, 256>>>(att_buf, w_proj, out, M_TOT, CDIM, CDIM);
    }
    // 4) Bias add in-place
    {
        size_t n4 = (size_t)M_TOT * CDIM / 4;
        int blocks = (int)((n4 + 255) / 256);
        bias_add_kernel<<<blocks, 256>>>(out, b_proj, n4);
    }
}